// round 4
// baseline (speedup 1.0000x reference)
#include <cuda_runtime.h>
#include <cstdint>

#define DIM   128
#define MAX_N 50000
#define MAX_E 800000
#define SCAN_T 1024

#define GEMM_RPB 128          // rows per block (M tile)
#define A_STRIDE 36           // float2 stride for A tile rows (32 + pad)
#define B_STRIDE 132          // float2 stride for B tile rows (128 + pad)
#define SMEM_F2  (128 * A_STRIDE + 32 * B_STRIDE)
#define SMEM_BYTES (SMEM_F2 * 8 + 128 * 4)

// ---------------------------------------------------------------------------
// Scratch (no allocations allowed). 16B-aligned for float4 access.
// ---------------------------------------------------------------------------
__device__ __align__(16) float g_aggr[MAX_N * DIM];
__device__ __align__(16) float g_h[MAX_N * DIM];
__device__ int   g_deg[MAX_N];
__device__ int   g_row[MAX_N];
__device__ int   g_cursor[MAX_N];
__device__ int   g_csr[MAX_E];

// ---------------------------------------------------------------------------
// CSR construction
// ---------------------------------------------------------------------------
__global__ void zero_counts_kernel(int n_nodes) {
    int i = blockIdx.x * blockDim.x + threadIdx.x;
    if (i < n_nodes) { g_deg[i] = 0; g_cursor[i] = 0; }
}

__global__ void degree_kernel(const int* __restrict__ tgt, int E, int n_nodes) {
    int e = blockIdx.x * blockDim.x + threadIdx.x;
    if (e < E) {
        int d = tgt[e];
        if ((unsigned)d < (unsigned)n_nodes) atomicAdd(&g_deg[d], 1);
    }
}

__global__ void __launch_bounds__(SCAN_T)
scan_kernel(int n_nodes) {
    __shared__ int partial[SCAN_T];
    const int t = threadIdx.x;
    const int C = (n_nodes + SCAN_T - 1) / SCAN_T;
    const int start = t * C;
    const int end   = min(start + C, n_nodes);

    int s = 0;
    for (int i = start; i < end; i++) s += g_deg[i];
    partial[t] = s;
    __syncthreads();

    for (int off = 1; off < SCAN_T; off <<= 1) {
        int v = 0;
        if (t >= off) v = partial[t - off];
        __syncthreads();
        if (t >= off) partial[t] += v;
        __syncthreads();
    }

    int excl = (t == 0) ? 0 : partial[t - 1];
    for (int i = start; i < end; i++) {
        g_row[i] = excl;
        excl += g_deg[i];
    }
}

__global__ void fill_kernel(const int* __restrict__ src,
                            const int* __restrict__ tgt, int E, int n_nodes) {
    int e = blockIdx.x * blockDim.x + threadIdx.x;
    if (e < E) {
        int d = tgt[e];
        int s = src[e];
        if ((unsigned)d < (unsigned)n_nodes && (unsigned)s < (unsigned)n_nodes) {
            int pos = atomicAdd(&g_cursor[d], 1);
            g_csr[g_row[d] + pos] = s;
        }
    }
}

// ---------------------------------------------------------------------------
// Aggregation: one warp per node (unchanged; ~L2-roofline bound)
// ---------------------------------------------------------------------------
__global__ void aggregate_kernel(const float* __restrict__ xin,
                                 int use_h, int n_nodes) {
    int warp = (blockIdx.x * blockDim.x + threadIdx.x) >> 5;
    int lane = threadIdx.x & 31;
    if (warp >= n_nodes) return;

    const float* __restrict__ X = use_h ? g_h : xin;
    const int base = g_row[warp];
    const int deg  = g_deg[warp];

    float ax = 0.f, ay = 0.f, az = 0.f, aw = 0.f;
    for (int i0 = 0; i0 < deg; i0 += 32) {
        int sv = 0;
        if (i0 + lane < deg) sv = g_csr[base + i0 + lane];
        int m = min(32, deg - i0);
        for (int j = 0; j < m; j++) {
            int s = __shfl_sync(0xffffffffu, sv, j);
            float4 v = *reinterpret_cast<const float4*>(
                X + (size_t)s * DIM + lane * 4);
            ax += v.x; ay += v.y; az += v.z; aw += v.w;
        }
    }
    float inv = 1.0f / fmaxf((float)deg, 1.0f);
    float4 o = make_float4(ax * inv, ay * inv, az * inv, aw * inv);
    *reinterpret_cast<float4*>(g_aggr + (size_t)warp * DIM + lane * 4) = o;
}

// ---------------------------------------------------------------------------
// Tensor-core GEMM (tf32 3-term split) + bias + relu.
//   out[n,j] = relu( X[n,:]@W[0:128,j] + aggr[n,:]@W[128:256,j] + b[j] )
// Block: 256 thr = 8 warps (4 m-warps x 2 n-warps). Block tile 128x128, K=256.
// Warp tile m32 x n64 via mma.sync.m16n8k8.tf32; D += Ah*Bh + Ah*Bl + Al*Bh.
// Smem tiles hold (hi,lo) float2 per element, pad strides kill bank conflicts.
// ---------------------------------------------------------------------------
__device__ __forceinline__ uint32_t f2tf32(float f) {
    uint32_t u;
    asm("cvt.rna.tf32.f32 %0, %1;" : "=r"(u) : "f"(f));
    return u;
}
__device__ __forceinline__ float2 split_tf32(float f) {
    uint32_t hi = f2tf32(f);
    float hif = __uint_as_float(hi);
    uint32_t lo = f2tf32(f - hif);
    return make_float2(hif, __uint_as_float(lo));
}
__device__ __forceinline__ void mma_tf32(float* d, const uint32_t* a,
                                         const uint32_t* b) {
    asm volatile(
        "mma.sync.aligned.m16n8k8.row.col.f32.tf32.tf32.f32 "
        "{%0,%1,%2,%3}, {%4,%5,%6,%7}, {%8,%9}, {%0,%1,%2,%3};"
        : "+f"(d[0]), "+f"(d[1]), "+f"(d[2]), "+f"(d[3])
        : "r"(a[0]), "r"(a[1]), "r"(a[2]), "r"(a[3]), "r"(b[0]), "r"(b[1]));
}

__global__ void __launch_bounds__(256)
gemm_tc_kernel(const float* __restrict__ Xin,
               const float* __restrict__ W,   // [256,128] row-major
               const float* __restrict__ bias,
               float* __restrict__ outp,
               int use_h_in, int out_is_h, int n_nodes) {
    extern __shared__ float2 smem_f2[];
    float2* a_s = smem_f2;                       // [128][A_STRIDE]
    float2* b_s = smem_f2 + 128 * A_STRIDE;      // [32][B_STRIDE]
    float*  bia = (float*)(smem_f2 + SMEM_F2);   // [128]

    const float* __restrict__ X = use_h_in ? g_h : Xin;
    float* __restrict__ out = out_is_h ? g_h : outp;

    const int tid  = threadIdx.x;
    const int wid  = tid >> 5;
    const int lane = tid & 31;
    const int wm   = wid >> 1;          // 0..3
    const int wn   = wid & 1;           // 0..1
    const int g    = lane >> 2;         // 0..7
    const int tq   = lane & 3;          // 0..3
    const int row0 = blockIdx.x * GEMM_RPB;

    if (tid < 128) bia[tid] = bias[tid];

    float acc[2][8][4];
#pragma unroll
    for (int i = 0; i < 2; i++)
#pragma unroll
        for (int j = 0; j < 8; j++)
#pragma unroll
            for (int c = 0; c < 4; c++) acc[i][j][c] = 0.0f;

    for (int kt = 0; kt < 2 * DIM; kt += 32) {
        __syncthreads();
        // --- A tile: 128 rows x 32 k, split to (hi,lo) ---
        {
            const bool agg = (kt >= DIM);
            const int kb = agg ? (kt - DIM) : kt;
            const float* __restrict__ sp = agg ? g_aggr : X;
#pragma unroll
            for (int i = 0; i < 4; i++) {
                int idx = tid + 256 * i;      // float4 idx, 8 per row
                int r = idx >> 3, c4 = idx & 7;
                int gr = row0 + r;
                float4 v = make_float4(0.f, 0.f, 0.f, 0.f);
                if (gr < n_nodes)
                    v = reinterpret_cast<const float4*>(
                            sp + (size_t)gr * DIM + kb)[c4];
                float2* dst = a_s + r * A_STRIDE + c4 * 4;
                dst[0] = split_tf32(v.x);
                dst[1] = split_tf32(v.y);
                dst[2] = split_tf32(v.z);
                dst[3] = split_tf32(v.w);
            }
        }
        // --- B tile: 32 k x 128 n from W, split to (hi,lo) ---
        {
#pragma unroll
            for (int i = 0; i < 4; i++) {
                int idx = tid + 256 * i;      // float4 idx, 32 per row
                int r = idx >> 5, c4 = idx & 31;
                float4 v = reinterpret_cast<const float4*>(
                    W + (size_t)(kt + r) * DIM)[c4];
                float2* dst = b_s + r * B_STRIDE + c4 * 4;
                dst[0] = split_tf32(v.x);
                dst[1] = split_tf32(v.y);
                dst[2] = split_tf32(v.z);
                dst[3] = split_tf32(v.w);
            }
        }
        __syncthreads();

#pragma unroll
        for (int k8 = 0; k8 < 32; k8 += 8) {
            uint32_t Ah[2][4], Al[2][4];
#pragma unroll
            for (int i = 0; i < 2; i++) {
                int rb = wm * 32 + i * 16;
                float2 f0 = a_s[(rb + g)     * A_STRIDE + k8 + tq];
                float2 f1 = a_s[(rb + g + 8) * A_STRIDE + k8 + tq];
                float2 f2 = a_s[(rb + g)     * A_STRIDE + k8 + tq + 4];
                float2 f3 = a_s[(rb + g + 8) * A_STRIDE + k8 + tq + 4];
                Ah[i][0] = __float_as_uint(f0.x); Al[i][0] = __float_as_uint(f0.y);
                Ah[i][1] = __float_as_uint(f1.x); Al[i][1] = __float_as_uint(f1.y);
                Ah[i][2] = __float_as_uint(f2.x); Al[i][2] = __float_as_uint(f2.y);
                Ah[i][3] = __float_as_uint(f3.x); Al[i][3] = __float_as_uint(f3.y);
            }
#pragma unroll
            for (int j = 0; j < 8; j++) {
                int col = wn * 64 + j * 8 + g;
                float2 h0 = b_s[(k8 + tq)     * B_STRIDE + col];
                float2 h1 = b_s[(k8 + tq + 4) * B_STRIDE + col];
                uint32_t Bh[2], Bl[2];
                Bh[0] = __float_as_uint(h0.x); Bl[0] = __float_as_uint(h0.y);
                Bh[1] = __float_as_uint(h1.x); Bl[1] = __float_as_uint(h1.y);
#pragma unroll
                for (int i = 0; i < 2; i++) {
                    mma_tf32(acc[i][j], Ah[i], Bh);
                    mma_tf32(acc[i][j], Ah[i], Bl);
                    mma_tf32(acc[i][j], Al[i], Bh);
                }
            }
        }
    }

    // --- epilogue: bias + relu, float2 stores ---
#pragma unroll
    for (int i = 0; i < 2; i++) {
        int ra = row0 + wm * 32 + i * 16 + g;
        int rb = ra + 8;
#pragma unroll
        for (int j = 0; j < 8; j++) {
            int col = wn * 64 + j * 8 + 2 * tq;
            float bx = bia[col], by = bia[col + 1];
            if (ra < n_nodes) {
                float2 o = make_float2(fmaxf(acc[i][j][0] + bx, 0.f),
                                       fmaxf(acc[i][j][1] + by, 0.f));
                *reinterpret_cast<float2*>(out + (size_t)ra * DIM + col) = o;
            }
            if (rb < n_nodes) {
                float2 o = make_float2(fmaxf(acc[i][j][2] + bx, 0.f),
                                       fmaxf(acc[i][j][3] + by, 0.f));
                *reinterpret_cast<float2*>(out + (size_t)rb * DIM + col) = o;
            }
        }
    }
}

// ---------------------------------------------------------------------------
// Launch
// ---------------------------------------------------------------------------
extern "C" void kernel_launch(void* const* d_in, const int* in_sizes, int n_in,
                              void* d_out, int out_size) {
    const float* x  = (const float*)d_in[0];
    const int*   ei = (const int*)d_in[1];   // int32 (JAX x64 disabled)
    const float* W1 = (const float*)d_in[2];
    const float* b1 = (const float*)d_in[3];
    const float* W2 = (const float*)d_in[4];
    const float* b2 = (const float*)d_in[5];
    float* out = (float*)d_out;

    const int n_nodes = in_sizes[0] / DIM;   // 50000
    const int E       = in_sizes[1] / 2;     // 800000
    const int* src = ei;
    const int* tgt = ei + E;

    static int smem_set = 0;
    if (!smem_set) {
        cudaFuncSetAttribute(gemm_tc_kernel,
                             cudaFuncAttributeMaxDynamicSharedMemorySize,
                             SMEM_BYTES);
        smem_set = 1;
    }

    const int threads = 256;
    const int nb = (n_nodes + threads - 1) / threads;
    const int eb = (E + threads - 1) / threads;
    const int ab = ((n_nodes * 32) + threads - 1) / threads;
    const int gb = (n_nodes + GEMM_RPB - 1) / GEMM_RPB;

    // CSR build (shared by both layers)
    zero_counts_kernel<<<nb, threads>>>(n_nodes);
    degree_kernel<<<eb, threads>>>(tgt, E, n_nodes);
    scan_kernel<<<1, SCAN_T>>>(n_nodes);
    fill_kernel<<<eb, threads>>>(src, tgt, E, n_nodes);

    // layer 1
    aggregate_kernel<<<ab, threads>>>(x, 0, n_nodes);
    gemm_tc_kernel<<<gb, threads, SMEM_BYTES>>>(x, W1, b1, out, 0, 1, n_nodes);

    // layer 2
    aggregate_kernel<<<ab, threads>>>(x, 1, n_nodes);
    gemm_tc_kernel<<<gb, threads, SMEM_BYTES>>>(x, W2, b2, out, 1, 0, n_nodes);
}

// round 5
// speedup vs baseline: 1.6395x; 1.6395x over previous
#include <cuda_runtime.h>
#include <cuda_bf16.h>
#include <cstdint>

#define DIM   128
#define MAX_N 50000
#define MAX_E 800000

#define GEMM_RPB 128
#define AS 20                 // smem row stride in u32 words (32 bf16 = 16w + 4 pad)

// ---------------------------------------------------------------------------
// Scratch (no allocations allowed)
// ---------------------------------------------------------------------------
__device__ __align__(16) float g_h[MAX_N * DIM];             // layer-1 output f32
__device__ __align__(16) __nv_bfloat16 g_xhi[MAX_N * DIM];
__device__ __align__(16) __nv_bfloat16 g_xlo[MAX_N * DIM];
__device__ __align__(16) __nv_bfloat16 g_hhi[MAX_N * DIM];
__device__ __align__(16) __nv_bfloat16 g_hlo[MAX_N * DIM];
__device__ __align__(16) __nv_bfloat16 g_ahi[MAX_N * DIM];
__device__ __align__(16) __nv_bfloat16 g_alo[MAX_N * DIM];
__device__ __align__(16) __nv_bfloat16 g_wthi[2 * DIM * 2 * DIM]; // [layer][n=128][k=256]
__device__ __align__(16) __nv_bfloat16 g_wtlo[2 * DIM * 2 * DIM];
__device__ int g_deg[MAX_N];
__device__ int g_row[MAX_N];
__device__ int g_cursor[MAX_N];
__device__ int g_csr[MAX_E];
__device__ int g_total;

// ---------------------------------------------------------------------------
// Helpers
// ---------------------------------------------------------------------------
__device__ __forceinline__ uint32_t pack_bf2(float a, float b) {
    __nv_bfloat162 t = __floats2bfloat162_rn(a, b);
    return *reinterpret_cast<uint32_t*>(&t);
}
__device__ __forceinline__ void split1(float v, float& hi, float& lo) {
    __nv_bfloat16 h = __float2bfloat16_rn(v);
    hi = __bfloat162float(h);
    lo = v - hi;
}
__device__ __forceinline__ void mma_bf16(float* d, const uint32_t* a,
                                         const uint32_t* b) {
    asm volatile(
        "mma.sync.aligned.m16n8k16.row.col.f32.bf16.bf16.f32 "
        "{%0,%1,%2,%3}, {%4,%5,%6,%7}, {%8,%9}, {%0,%1,%2,%3};"
        : "+f"(d[0]), "+f"(d[1]), "+f"(d[2]), "+f"(d[3])
        : "r"(a[0]), "r"(a[1]), "r"(a[2]), "r"(a[3]), "r"(b[0]), "r"(b[1]));
}

// ---------------------------------------------------------------------------
// CSR construction
// ---------------------------------------------------------------------------
__global__ void zero_counts_kernel(int n_nodes) {
    int i = blockIdx.x * blockDim.x + threadIdx.x;
    if (i < n_nodes) { g_deg[i] = 0; g_cursor[i] = 0; }
    if (i == 0) g_total = 0;
}

__global__ void degree_kernel(const int* __restrict__ tgt, int E, int n_nodes) {
    int e = blockIdx.x * blockDim.x + threadIdx.x;
    if (e < E) {
        int d = tgt[e];
        if ((unsigned)d < (unsigned)n_nodes) atomicAdd(&g_deg[d], 1);
    }
}

// Parallel row reservation (replaces single-block scan). Row placement order is
// arbitrary but each node's list is contiguous -> per-node sums unchanged.
__global__ void reserve_kernel(int n_nodes) {
    int i = blockIdx.x * blockDim.x + threadIdx.x;
    if (i < n_nodes) g_row[i] = atomicAdd(&g_total, g_deg[i]);
}

__global__ void fill_kernel(const int* __restrict__ src,
                            const int* __restrict__ tgt, int E, int n_nodes) {
    int e = blockIdx.x * blockDim.x + threadIdx.x;
    if (e < E) {
        int d = tgt[e];
        int s = src[e];
        if ((unsigned)d < (unsigned)n_nodes && (unsigned)s < (unsigned)n_nodes) {
            int pos = atomicAdd(&g_cursor[d], 1);
            g_csr[g_row[d] + pos] = s;
        }
    }
}

// ---------------------------------------------------------------------------
// Split x -> bf16 hi/lo
// ---------------------------------------------------------------------------
__global__ void split_x_kernel(const float* __restrict__ X, int n4) {
    int i = blockIdx.x * blockDim.x + threadIdx.x;
    if (i >= n4) return;
    float4 v = reinterpret_cast<const float4*>(X)[i];
    float hx, lx, hy, ly, hz, lz, hw, lw;
    split1(v.x, hx, lx); split1(v.y, hy, ly);
    split1(v.z, hz, lz); split1(v.w, hw, lw);
    uint2 hi = make_uint2(pack_bf2(hx, hy), pack_bf2(hz, hw));
    uint2 lo = make_uint2(pack_bf2(lx, ly), pack_bf2(lz, lw));
    reinterpret_cast<uint2*>(g_xhi)[i] = hi;
    reinterpret_cast<uint2*>(g_xlo)[i] = lo;
}

// Split + transpose W ([256,128] row-major -> [128 n][256 k]) for both layers
__global__ void split_w_kernel(const float* __restrict__ W1,
                               const float* __restrict__ W2) {
    int i = blockIdx.x * blockDim.x + threadIdx.x;   // 2*256*128 elems
    int layer = i >> 15;
    int idx = i & 32767;
    int k = idx >> 7;
    int n = idx & 127;
    float v = layer ? W2[idx] : W1[idx];
    float hi, lo;
    split1(v, hi, lo);
    size_t o = (size_t)layer * DIM * 2 * DIM + (size_t)n * 2 * DIM + k;
    g_wthi[o] = __float2bfloat16_rn(hi);
    g_wtlo[o] = __float2bfloat16_rn(lo);
}

// ---------------------------------------------------------------------------
// Aggregation: one warp per node; writes bf16 hi/lo mean directly.
// ---------------------------------------------------------------------------
__global__ void aggregate_kernel(const float* __restrict__ xin,
                                 int use_h, int n_nodes) {
    int warp = (blockIdx.x * blockDim.x + threadIdx.x) >> 5;
    int lane = threadIdx.x & 31;
    if (warp >= n_nodes) return;

    const float* __restrict__ X = use_h ? g_h : xin;
    const int base = g_row[warp];
    const int deg  = g_deg[warp];

    float ax = 0.f, ay = 0.f, az = 0.f, aw = 0.f;
    for (int i0 = 0; i0 < deg; i0 += 32) {
        int sv = 0;
        if (i0 + lane < deg) sv = g_csr[base + i0 + lane];
        int m = min(32, deg - i0);
#pragma unroll 4
        for (int j = 0; j < m; j++) {
            int s = __shfl_sync(0xffffffffu, sv, j);
            float4 v = *reinterpret_cast<const float4*>(
                X + (size_t)s * DIM + lane * 4);
            ax += v.x; ay += v.y; az += v.z; aw += v.w;
        }
    }
    float inv = 1.0f / fmaxf((float)deg, 1.0f);
    ax *= inv; ay *= inv; az *= inv; aw *= inv;

    float hx, lx, hy, ly, hz, lz, hw, lw;
    split1(ax, hx, lx); split1(ay, hy, ly);
    split1(az, hz, lz); split1(aw, hw, lw);
    size_t o = ((size_t)warp * DIM + lane * 4) >> 1;   // uint index (2 bf16/u32)
    reinterpret_cast<uint2*>(g_ahi)[o >> 1] =
        make_uint2(pack_bf2(hx, hy), pack_bf2(hz, hw));
    reinterpret_cast<uint2*>(g_alo)[o >> 1] =
        make_uint2(pack_bf2(lx, ly), pack_bf2(lz, lw));
}

// ---------------------------------------------------------------------------
// bf16 3-term tensor-core GEMM + bias + relu.
//   out[n,j] = relu( A[n,:] @ Wt[j,:] + b[j] ),  A = [X | aggr] (hi+lo pairs)
// 256 thr = 8 warps (4m x 2n); block tile 128x128; warp tile m32 x n64.
// D += Ah*Bh + Ah*Bl + Al*Bh  via mma.m16n8k16.bf16.
// ---------------------------------------------------------------------------
__global__ void __launch_bounds__(256)
gemm_bf16_kernel(const __nv_bfloat16* __restrict__ Ahi0,  // first-half A (x or h)
                 const __nv_bfloat16* __restrict__ Alo0,
                 const __nv_bfloat16* __restrict__ Whi,   // [128 n][256 k]
                 const __nv_bfloat16* __restrict__ Wlo,
                 const float* __restrict__ bias,
                 float* __restrict__ out,                 // f32 [N,128]
                 __nv_bfloat16* __restrict__ Ohi,         // optional bf16 split out
                 __nv_bfloat16* __restrict__ Olo,
                 int n_nodes) {
    __shared__ uint32_t a_hi_s[128 * AS];
    __shared__ uint32_t a_lo_s[128 * AS];
    __shared__ uint32_t w_hi_s[128 * AS];
    __shared__ uint32_t w_lo_s[128 * AS];
    __shared__ float bia[128];

    const int tid  = threadIdx.x;
    const int wid  = tid >> 5;
    const int lane = tid & 31;
    const int wm   = wid >> 1;
    const int wn   = wid & 1;
    const int g    = lane >> 2;
    const int tq   = lane & 3;
    const int row0 = blockIdx.x * GEMM_RPB;

    if (tid < 128) bia[tid] = bias[tid];

    float acc[2][8][4];
#pragma unroll
    for (int i = 0; i < 2; i++)
#pragma unroll
        for (int j = 0; j < 8; j++)
#pragma unroll
            for (int c = 0; c < 4; c++) acc[i][j][c] = 0.0f;

    const int r    = tid >> 1;       // tile row / n for loads
    const int half = tid & 1;        // 16-bf16 half

    for (int kt = 0; kt < 2 * DIM; kt += 32) {
        const bool agg = (kt >= DIM);
        const int  kb  = kt & (DIM - 1);
        const __nv_bfloat16* __restrict__ Ah = agg ? g_ahi : Ahi0;
        const __nv_bfloat16* __restrict__ Al = agg ? g_alo : Alo0;

        __syncthreads();
        // A tile: 128 rows x 32 k (hi+lo)
        {
            int gr = row0 + r;
            uint4 vh0 = {0,0,0,0}, vh1 = {0,0,0,0}, vl0 = {0,0,0,0}, vl1 = {0,0,0,0};
            if (gr < n_nodes) {
                const uint4* ph = reinterpret_cast<const uint4*>(
                    Ah + (size_t)gr * DIM + kb) + half * 2;
                const uint4* pl = reinterpret_cast<const uint4*>(
                    Al + (size_t)gr * DIM + kb) + half * 2;
                vh0 = ph[0]; vh1 = ph[1];
                vl0 = pl[0]; vl1 = pl[1];
            }
            uint32_t* dh = a_hi_s + r * AS + half * 8;
            uint32_t* dl = a_lo_s + r * AS + half * 8;
            reinterpret_cast<uint4*>(dh)[0] = vh0;
            reinterpret_cast<uint4*>(dh)[1] = vh1;
            reinterpret_cast<uint4*>(dl)[0] = vl0;
            reinterpret_cast<uint4*>(dl)[1] = vl1;
        }
        // W tile: 128 n x 32 k (hi+lo), Wt is [n][256]
        {
            const uint4* ph = reinterpret_cast<const uint4*>(
                Whi + (size_t)r * 2 * DIM + kt) + half * 2;
            const uint4* pl = reinterpret_cast<const uint4*>(
                Wlo + (size_t)r * 2 * DIM + kt) + half * 2;
            uint32_t* dh = w_hi_s + r * AS + half * 8;
            uint32_t* dl = w_lo_s + r * AS + half * 8;
            reinterpret_cast<uint4*>(dh)[0] = ph[0];
            reinterpret_cast<uint4*>(dh)[1] = ph[1];
            reinterpret_cast<uint4*>(dl)[0] = pl[0];
            reinterpret_cast<uint4*>(dl)[1] = pl[1];
        }
        __syncthreads();

#pragma unroll
        for (int k16 = 0; k16 < 32; k16 += 16) {
            const int kw = (k16 >> 1) + tq;
            uint32_t Afh[2][4], Afl[2][4];
#pragma unroll
            for (int i = 0; i < 2; i++) {
                int r0 = wm * 32 + i * 16 + g;
                Afh[i][0] = a_hi_s[r0 * AS + kw];
                Afh[i][1] = a_hi_s[(r0 + 8) * AS + kw];
                Afh[i][2] = a_hi_s[r0 * AS + kw + 4];
                Afh[i][3] = a_hi_s[(r0 + 8) * AS + kw + 4];
                Afl[i][0] = a_lo_s[r0 * AS + kw];
                Afl[i][1] = a_lo_s[(r0 + 8) * AS + kw];
                Afl[i][2] = a_lo_s[r0 * AS + kw + 4];
                Afl[i][3] = a_lo_s[(r0 + 8) * AS + kw + 4];
            }
#pragma unroll
            for (int j = 0; j < 8; j++) {
                int c = wn * 64 + j * 8 + g;
                uint32_t Bh[2], Bl[2];
                Bh[0] = w_hi_s[c * AS + kw];
                Bh[1] = w_hi_s[c * AS + kw + 4];
                Bl[0] = w_lo_s[c * AS + kw];
                Bl[1] = w_lo_s[c * AS + kw + 4];
#pragma unroll
                for (int i = 0; i < 2; i++) {
                    mma_bf16(acc[i][j], Afh[i], Bh);
                    mma_bf16(acc[i][j], Afh[i], Bl);
                    mma_bf16(acc[i][j], Afl[i], Bh);
                }
            }
        }
    }

    // Epilogue: bias + relu; f32 store (+ optional bf16 hi/lo split store)
#pragma unroll
    for (int i = 0; i < 2; i++) {
        int ra = row0 + wm * 32 + i * 16 + g;
        int rb = ra + 8;
#pragma unroll
        for (int j = 0; j < 8; j++) {
            int col = wn * 64 + j * 8 + 2 * tq;
            float bx = bia[col], by = bia[col + 1];
            if (ra < n_nodes) {
                float ox = fmaxf(acc[i][j][0] + bx, 0.f);
                float oy = fmaxf(acc[i][j][1] + by, 0.f);
                *reinterpret_cast<float2*>(out + (size_t)ra * DIM + col) =
                    make_float2(ox, oy);
                if (Ohi) {
                    float hx, lx, hy, ly;
                    split1(ox, hx, lx); split1(oy, hy, ly);
                    *reinterpret_cast<uint32_t*>(Ohi + (size_t)ra * DIM + col) =
                        pack_bf2(hx, hy);
                    *reinterpret_cast<uint32_t*>(Olo + (size_t)ra * DIM + col) =
                        pack_bf2(lx, ly);
                }
            }
            if (rb < n_nodes) {
                float ox = fmaxf(acc[i][j][2] + bx, 0.f);
                float oy = fmaxf(acc[i][j][3] + by, 0.f);
                *reinterpret_cast<float2*>(out + (size_t)rb * DIM + col) =
                    make_float2(ox, oy);
                if (Ohi) {
                    float hx, lx, hy, ly;
                    split1(ox, hx, lx); split1(oy, hy, ly);
                    *reinterpret_cast<uint32_t*>(Ohi + (size_t)rb * DIM + col) =
                        pack_bf2(hx, hy);
                    *reinterpret_cast<uint32_t*>(Olo + (size_t)rb * DIM + col) =
                        pack_bf2(lx, ly);
                }
            }
        }
    }
}

// ---------------------------------------------------------------------------
// Launch
// ---------------------------------------------------------------------------
extern "C" void kernel_launch(void* const* d_in, const int* in_sizes, int n_in,
                              void* d_out, int out_size) {
    const float* x  = (const float*)d_in[0];
    const int*   ei = (const int*)d_in[1];   // int32 (JAX x64 disabled)
    const float* W1 = (const float*)d_in[2];
    const float* b1 = (const float*)d_in[3];
    const float* W2 = (const float*)d_in[4];
    const float* b2 = (const float*)d_in[5];
    float* out = (float*)d_out;

    const int n_nodes = in_sizes[0] / DIM;   // 50000
    const int E       = in_sizes[1] / 2;     // 800000
    const int* src = ei;
    const int* tgt = ei + E;

    float* h_ptr;  cudaGetSymbolAddress((void**)&h_ptr,  g_h);
    __nv_bfloat16 *xhi, *xlo, *hhi, *hlo, *whi, *wlo;
    cudaGetSymbolAddress((void**)&xhi, g_xhi);
    cudaGetSymbolAddress((void**)&xlo, g_xlo);
    cudaGetSymbolAddress((void**)&hhi, g_hhi);
    cudaGetSymbolAddress((void**)&hlo, g_hlo);
    cudaGetSymbolAddress((void**)&whi, g_wthi);
    cudaGetSymbolAddress((void**)&wlo, g_wtlo);

    const int threads = 256;
    const int nb = (n_nodes + threads - 1) / threads;
    const int eb = (E + threads - 1) / threads;
    const int ab = ((n_nodes * 32) + threads - 1) / threads;
    const int gb = (n_nodes + GEMM_RPB - 1) / GEMM_RPB;
    const int n4 = n_nodes * DIM / 4;
    const int sxb = (n4 + threads - 1) / threads;
    const int swb = (2 * 256 * 128 + threads - 1) / threads;
    const size_t wstride = (size_t)DIM * 2 * DIM;

    // CSR build + splits
    zero_counts_kernel<<<nb, threads>>>(n_nodes);
    degree_kernel<<<eb, threads>>>(tgt, E, n_nodes);
    reserve_kernel<<<nb, threads>>>(n_nodes);
    fill_kernel<<<eb, threads>>>(src, tgt, E, n_nodes);
    split_x_kernel<<<sxb, threads>>>(x, n4);
    split_w_kernel<<<swb, threads>>>(W1, W2);

    // layer 1
    aggregate_kernel<<<ab, threads>>>(x, 0, n_nodes);
    gemm_bf16_kernel<<<gb, threads>>>(xhi, xlo, whi, wlo, b1,
                                      h_ptr, hhi, hlo, n_nodes);

    // layer 2
    aggregate_kernel<<<ab, threads>>>(x, 1, n_nodes);
    gemm_bf16_kernel<<<gb, threads>>>(hhi, hlo, whi + wstride, wlo + wstride,
                                      b2, out, nullptr, nullptr, n_nodes);
}